// round 6
// baseline (speedup 1.0000x reference)
#include <cuda_runtime.h>
#include <cuda_bf16.h>
#include <stdint.h>

#define NUM_ROWS 16384
#define HDIM     2048
#define KSEL     4
#define NEXP     64
#define NTOT     (NUM_ROWS * KSEL)   /* 65536 expanded slots */
#define NCHUNK   512
#define CHUNK    128                 /* items per chunk */
#define NWARP    (CHUNK / 32)        /* 4 warps rank a chunk */

/* output layout (floats) */
#define X_OFF   0
#define RI_OFF  ((size_t)NTOT * HDIM)                 /* 134217728 */
#define CNT_OFF (RI_OFF + NTOT)                        /* +65536 */
#define SC_OFF  (CNT_OFF + NEXP)                       /* +64 */

/* scratch (no cudaMalloc allowed) */
__device__ int g_base[NCHUNK * NEXP];   /* stable per-chunk/per-expert bases */

/* ---- K1: fused histogram + scan, ONE block of 1024 threads ----
 * Per-chunk u8 histograms live in shared (512 chunks x 64 experts = 32KB),
 * so hist -> scan needs only a __syncthreads, not a kernel boundary.
 */
#define GRP 16
#define CPG (NCHUNK / GRP)   /* 32 chunks per scan group */
__global__ void __launch_bounds__(1024) k_prep(const int* __restrict__ eidx,
                                               float* __restrict__ out) {
    __shared__ unsigned char sh_cnt[NCHUNK * NEXP];   /* 32 KB */
    __shared__ int warpHist[32][NEXP];                /* 8 KB  */
    __shared__ int tot[NEXP];
    __shared__ int offs[NEXP];

    int t = threadIdx.x;
    int w = t >> 5, lane = t & 31;

    /* phase A: each warp histograms 16 chunks (128 items each) */
    for (int j = 0; j < 16; ++j) {
        int c = w * 16 + j;
        warpHist[w][lane] = 0;
        warpHist[w][lane + 32] = 0;
        __syncwarp();
        int4 ev = ((const int4*)eidx)[c * 32 + lane];   /* items 4*lane..4*lane+3 */
        atomicAdd(&warpHist[w][ev.x], 1);
        atomicAdd(&warpHist[w][ev.y], 1);
        atomicAdd(&warpHist[w][ev.z], 1);
        atomicAdd(&warpHist[w][ev.w], 1);
        __syncwarp();
        sh_cnt[c * NEXP + lane]      = (unsigned char)warpHist[w][lane];
        sh_cnt[c * NEXP + lane + 32] = (unsigned char)warpHist[w][lane + 32];
    }
    __syncthreads();

    /* phase B: scan. thread t: expert e = t>>4, group g = t&15 owns 32 chunks */
    int e = t >> 4;
    int g = t & (GRP - 1);

    int v[CPG];
    int partial = 0;
#pragma unroll
    for (int j = 0; j < CPG; ++j) {
        v[j] = sh_cnt[(g * CPG + j) * NEXP + e];
        partial += v[j];
    }
    int inc = partial;
#pragma unroll
    for (int d = 1; d < GRP; d <<= 1) {
        int y = __shfl_up_sync(0xffffffffu, inc, d, GRP);
        if (g >= d) inc += y;
    }
    if (g == GRP - 1) tot[e] = inc;
    __syncthreads();
    if (t == 0) {
        int run = 0;
        for (int j = 0; j < NEXP; ++j) { offs[j] = run; run += tot[j]; }
    }
    __syncthreads();
    if (t < NEXP) out[CNT_OFF + t] = (float)tot[t];

    int run = offs[e] + (inc - partial);
#pragma unroll
    for (int j = 0; j < CPG; ++j) {
        g_base[(g * CPG + j) * NEXP + e] = run;
        run += v[j];
    }
}

/* ---- K2: gather copy with in-block stable-rank resolve ----
 * 2048 blocks = 512 chunks x 4 sub-blocks. Each block redundantly ranks its
 * chunk's 128 slots (cheap, hidden), then copies its 32 rows with the proven
 * interleaved load->store pattern (low MLP_p1, avoids L1tex-queue spread).
 */
__global__ void __launch_bounds__(256) k_copy(const float* __restrict__ x,
                                              const int* __restrict__ eidx,
                                              const float* __restrict__ scale,
                                              float* __restrict__ out) {
    __shared__ int shcnt[NWARP][NEXP];
    __shared__ int sdest[CHUNK];

    int c = blockIdx.x >> 2;
    int q = blockIdx.x & 3;
    int t = threadIdx.x;

    ((int*)shcnt)[t] = 0;          /* 256 entries, one per thread */
    __syncthreads();

    if (t < CHUNK) {
        int i = c * CHUNK + t;
        int e = eidx[i];
        int w = t >> 5, lane = t & 31;
        unsigned m = __match_any_sync(0xffffffffu, e);
        int rank = __popc(m & ((1u << lane) - 1));
        if (rank == 0) shcnt[w][e] = __popc(m);
        __syncthreads();
        int off = 0;
#pragma unroll
        for (int w2 = 0; w2 < NWARP; ++w2)
            if (w2 < w) off += shcnt[w2][e];
        int d = g_base[c * NEXP + e] + off + rank;
        sdest[t] = d;
        if (q == 0) {
            out[RI_OFF + i] = (float)d;
            out[SC_OFF + d] = scale[i >> 2];
        }
    } else {
        __syncthreads();
    }
    __syncthreads();

    /* copy 32 rows: slots [q*32, q*32+32) of chunk c */
    int r0 = q * 32;
#pragma unroll 2
    for (int r = 0; r < 32; ++r) {
        int slot = r0 + r;
        int i = c * CHUNK + slot;
        int src = i >> 2;
        int d = sdest[slot];
        const float4* __restrict__ s = (const float4*)(x + (size_t)src * HDIM);
        float4* __restrict__ o = (float4*)(out + X_OFF + (size_t)d * HDIM);
        o[t]       = s[t];
        o[t + 256] = s[t + 256];
    }
}

extern "C" void kernel_launch(void* const* d_in, const int* in_sizes, int n_in,
                              void* d_out, int out_size) {
    const float* x     = (const float*)d_in[0];
    const int*   eidx  = (const int*)d_in[1];
    const float* scale = (const float*)d_in[2];
    float* out = (float*)d_out;

    k_prep<<<1, 1024>>>(eidx, out);
    k_copy<<<NCHUNK * 4, 256>>>(x, eidx, scale, out);
}

// round 7
// speedup vs baseline: 1.2008x; 1.2008x over previous
#include <cuda_runtime.h>
#include <cuda_bf16.h>
#include <stdint.h>

#define NUM_ROWS 16384
#define HDIM     2048
#define KSEL     4
#define NEXP     64
#define NTOT     (NUM_ROWS * KSEL)   /* 65536 expanded slots */
#define NCHUNK   256
#define CHUNK    (NTOT / NCHUNK)     /* 256 items per chunk */
#define NWARP    (CHUNK / 32)        /* 8 warps per chunk block */

/* output layout (floats) */
#define X_OFF   0
#define RI_OFF  ((size_t)NTOT * HDIM)                 /* 134217728 */
#define CNT_OFF (RI_OFF + NTOT)                        /* +65536 */
#define SC_OFF  (CNT_OFF + NEXP)                       /* +64 */

/* scratch (no cudaMalloc allowed) */
__device__ int g_chunkCounts[NCHUNK * NEXP];  /* K1: counts; K2: stable bases */
__device__ int g_rank[NTOT];                  /* intra-chunk stable rank      */

/* ---- K1: per-chunk histogram + intra-chunk stable rank ---- */
__global__ void __launch_bounds__(CHUNK) k_rank(const int* __restrict__ eidx) {
    __shared__ int shcnt[NWARP][NEXP];
    int t = threadIdx.x;
    int c = blockIdx.x;
    int w = t >> 5, lane = t & 31;

    for (int j = t; j < NWARP * NEXP; j += CHUNK)
        ((int*)shcnt)[j] = 0;
    __syncthreads();

    int i = c * CHUNK + t;
    int e = eidx[i];
    unsigned m = __match_any_sync(0xffffffffu, e);
    int rank = __popc(m & ((1u << lane) - 1));
    if (rank == 0) shcnt[w][e] = __popc(m);
    __syncthreads();

    int off = 0;
#pragma unroll
    for (int w2 = 0; w2 < NWARP; ++w2)
        if (w2 < w) off += shcnt[w2][e];
    g_rank[i] = off + rank;

    if (t < NEXP) {
        int s = 0;
#pragma unroll
        for (int w2 = 0; w2 < NWARP; ++w2) s += shcnt[w2][t];
        g_chunkCounts[c * NEXP + t] = s;
    }
}

/* ---- K2: parallel scan -> stable per-chunk/per-expert bases + counts ---- */
#define GRP 16
#define CPG (NCHUNK / GRP)   /* 16 chunks per group */
__global__ void __launch_bounds__(1024) k_scan(float* __restrict__ out) {
#if __CUDA_ARCH__ >= 900
    cudaGridDependencySynchronize();
#endif
    __shared__ int tot[NEXP];
    __shared__ int offs[NEXP];
    int t = threadIdx.x;
    int e = t >> 4;           /* expert 0..63 */
    int g = t & (GRP - 1);    /* chunk-group 0..15 */

    int v[CPG];
    int partial = 0;
#pragma unroll
    for (int j = 0; j < CPG; ++j) {
        v[j] = g_chunkCounts[(g * CPG + j) * NEXP + e];
        partial += v[j];
    }

    int inc = partial;
#pragma unroll
    for (int d = 1; d < GRP; d <<= 1) {
        int y = __shfl_up_sync(0xffffffffu, inc, d, GRP);
        if (g >= d) inc += y;
    }
    if (g == GRP - 1) tot[e] = inc;
    __syncthreads();

    if (t == 0) {
        int run = 0;
        for (int j = 0; j < NEXP; ++j) { offs[j] = run; run += tot[j]; }
    }
    __syncthreads();
    if (t < NEXP) out[CNT_OFF + t] = (float)tot[t];

    int run = offs[e] + (inc - partial);   /* exclusive base for this group */
#pragma unroll
    for (int j = 0; j < CPG; ++j) {
        g_chunkCounts[(g * CPG + j) * NEXP + e] = run;
        run += v[j];
    }
}

/* ---- K3: big gather copy + final dest resolve + small outputs ---- */
__global__ void __launch_bounds__(128) k_copy(const float* __restrict__ x,
                                              const int* __restrict__ eidx,
                                              const float* __restrict__ scale,
                                              float* __restrict__ out) {
#if __CUDA_ARCH__ >= 900
    cudaGridDependencySynchronize();
#endif
    int i = blockIdx.x;          /* expanded slot 0..NTOT-1 */
    int e = __ldg(eidx + i);
    int d = g_chunkCounts[(i >> 8) * NEXP + e] + g_rank[i];
    int src = i >> 2;

    const float4* __restrict__ s = (const float4*)(x + (size_t)src * HDIM);
    float4* __restrict__ o = (float4*)(out + X_OFF + (size_t)d * HDIM);
#pragma unroll
    for (int j = 0; j < 4; ++j) {
        int idx = threadIdx.x + j * 128;   /* 512 float4 per row */
        o[idx] = s[idx];
    }
    if (threadIdx.x == 0) {
        out[RI_OFF + i] = (float)d;
        out[SC_OFF + d] = scale[src];
    }
}

extern "C" void kernel_launch(void* const* d_in, const int* in_sizes, int n_in,
                              void* d_out, int out_size) {
    const float* x     = (const float*)d_in[0];
    const int*   eidx  = (const int*)d_in[1];
    const float* scale = (const float*)d_in[2];
    float* out = (float*)d_out;

    /* K1: plain launch */
    k_rank<<<NCHUNK, CHUNK>>>(eidx);

    /* K2, K3: programmatic dependent launches — launch overhead (and most of
     * k_scan) overlaps the predecessor; correctness via device-side
     * cudaGridDependencySynchronize() at kernel entry. */
    cudaLaunchAttribute attr[1];
    attr[0].id = cudaLaunchAttributeProgrammaticStreamSerialization;
    attr[0].val.programmaticStreamSerializationAllowed = 1;

    {
        cudaLaunchConfig_t cfg = {};
        cfg.gridDim  = dim3(1, 1, 1);
        cfg.blockDim = dim3(1024, 1, 1);
        cfg.dynamicSmemBytes = 0;
        cfg.stream = 0;
        cfg.attrs = attr;
        cfg.numAttrs = 1;
        cudaLaunchKernelEx(&cfg, k_scan, out);
    }
    {
        cudaLaunchConfig_t cfg = {};
        cfg.gridDim  = dim3(NTOT, 1, 1);
        cfg.blockDim = dim3(128, 1, 1);
        cfg.dynamicSmemBytes = 0;
        cfg.stream = 0;
        cfg.attrs = attr;
        cfg.numAttrs = 1;
        cudaLaunchKernelEx(&cfg, k_copy, x, eidx, scale, out);
    }
}